// round 6
// baseline (speedup 1.0000x reference)
#include <cuda_runtime.h>
#include <stdint.h>

#define B_  32
#define H_  512
#define W_  512
#define PIX_PER_IMG (H_ * W_)                    // 262144
#define CHUNKS 32                                // moments blocks per batch
#define F4_PER_CHUNK (PIX_PER_IMG / CHUNKS / 4)  // 2048 float4 per block
#define F4_PER_THREAD (F4_PER_CHUNK / 256)       // 8  (32 data regs, no spill)

// Scratch (no allocations allowed)
__device__ float        g_part[B_ * CHUNKS * 3];
__device__ int          g_shift[B_ * 2];         // (dx, dy) per batch
__device__ unsigned int g_cnt[B_];               // zero-init; self-reset each launch

// ---------------------------------------------------------------------------
// Stage 1 (fused): per-chunk partial moments of mk + last-block finalize.
// Deterministic: fixed per-thread accumulation order, butterfly shuffle
// reduce, fixed-order finalize tree regardless of arrival order.
// ---------------------------------------------------------------------------
__global__ __launch_bounds__(256) void moments_fused(const float* __restrict__ mk)
{
    const int b     = blockIdx.y;
    const int chunk = blockIdx.x;       // 0..31
    const int t     = threadIdx.x;      // 0..255
    const int lane  = t & 31;
    const int wid   = t >> 5;           // 0..7

    const float4* base =
        (const float4*)(mk + (size_t)b * PIX_PER_IMG) + chunk * F4_PER_CHUNK;

    // Front-batch 8 independent loads (MLP_p1=8), then accumulate fixed-order.
    float4 v[F4_PER_THREAD];
#pragma unroll
    for (int i = 0; i < F4_PER_THREAD; i++)
        v[i] = base[t + i * 256];

    float s0 = 0.f, s1 = 0.f, s2 = 0.f;
#pragma unroll
    for (int i = 0; i < F4_PER_THREAD; i++) {
        const int p = chunk * (F4_PER_CHUNK * 4) + (t + i * 256) * 4;
        const int h = p >> 9;
        const int w = p & (W_ - 1);
        const float ry  = (float)(h - (H_ / 2));
        const float rx0 = (float)(w - (W_ / 2));
        const float sum = v[i].x + v[i].y + v[i].z + v[i].w;
        s0 += sum;
        s2 += ry * sum;
        s1 += rx0 * v[i].x + (rx0 + 1.f) * v[i].y + (rx0 + 2.f) * v[i].z
            + (rx0 + 3.f) * v[i].w;
    }

    // Warp butterfly reduce (deterministic fixed order)
#pragma unroll
    for (int m = 16; m > 0; m >>= 1) {
        s0 += __shfl_xor_sync(0xffffffffu, s0, m);
        s1 += __shfl_xor_sync(0xffffffffu, s1, m);
        s2 += __shfl_xor_sync(0xffffffffu, s2, m);
    }

    __shared__ float w0[8], w1[8], w2[8];
    if (lane == 0) { w0[wid] = s0; w1[wid] = s1; w2[wid] = s2; }
    __syncthreads();

    __shared__ bool isLast;
    if (t == 0) {
        float r0 = 0.f, r1 = 0.f, r2 = 0.f;
#pragma unroll
        for (int i = 0; i < 8; i++) { r0 += w0[i]; r1 += w1[i]; r2 += w2[i]; }
        const int o = (b * CHUNKS + chunk) * 3;
        g_part[o + 0] = r0;
        g_part[o + 1] = r1;
        g_part[o + 2] = r2;
        __threadfence();
        isLast = (atomicAdd(&g_cnt[b], 1u) == CHUNKS - 1);
    }
    __syncthreads();

    if (isLast) {
        __shared__ float f0[CHUNKS], f1[CHUNKS], f2[CHUNKS];
        if (t < CHUNKS) {
            const int o = (b * CHUNKS + t) * 3;
            f0[t] = g_part[o + 0];
            f1[t] = g_part[o + 1];
            f2[t] = g_part[o + 2];
        }
        __syncthreads();
#pragma unroll
        for (int st = CHUNKS / 2; st > 0; st >>= 1) {
            if (t < st) {
                f0[t] += f0[t + st];
                f1[t] += f1[t + st];
                f2[t] += f2[t + st];
            }
            __syncthreads();
        }
        if (t == 0) {
            const float m00 = fmaxf(0.001f, f0[0]);
            // rintf = round-half-even, matching jnp.round
            g_shift[b * 2 + 0] = (int)rintf(f1[0] / m00);   // dx
            g_shift[b * 2 + 1] = (int)rintf(f2[0] / m00);   // dy
            g_cnt[b] = 0u;      // self-reset -> state-clean for next replay
            __threadfence();
        }
    }
}

// ---------------------------------------------------------------------------
// Stage 2: shifted copy. 8 pixels (8x float4) per thread; independent loads
// front-batched for MLP=8; fully coalesced within each 256-pixel slab.
// out[b,h,w] = x[b, h+dy, w+dx] if in-bounds else 0   (clamped-pad semantics)
// ---------------------------------------------------------------------------
#define SHIFT_ELEMS 8
__global__ __launch_bounds__(256) void shift_kernel(const float4* __restrict__ x,
                                                    float4* __restrict__ out)
{
    const int b    = blockIdx.y;
    const int base = blockIdx.x * (256 * SHIFT_ELEMS);   // pixel base in image
    const int t    = threadIdx.x;

    const int dx = g_shift[b * 2 + 0];
    const int dy = g_shift[b * 2 + 1];

    const float4* xb = x + ((size_t)b << 18);
    float4* ob       = out + ((size_t)b << 18);

    float4 v[SHIFT_ELEMS];
#pragma unroll
    for (int k = 0; k < SHIFT_ELEMS; k++) {
        const int p = base + k * 256 + t;
        const int h = p >> 9;
        const int w = p & (W_ - 1);
        const int sh = h + dy;
        const int sw = w + dx;
        v[k] = make_float4(0.f, 0.f, 0.f, 0.f);
        if ((unsigned)sh < (unsigned)H_ && (unsigned)sw < (unsigned)W_)
            v[k] = xb[(sh << 9) + sw];
    }
#pragma unroll
    for (int k = 0; k < SHIFT_ELEMS; k++)
        ob[base + k * 256 + t] = v[k];
}

// ---------------------------------------------------------------------------
extern "C" void kernel_launch(void* const* d_in, const int* in_sizes, int n_in,
                              void* d_out, int out_size)
{
    const float* x  = (const float*)d_in[0];   // [32,512,512,4]
    const float* mk = (const float*)d_in[1];   // [32,512,512,1]

    dim3 g1(CHUNKS, B_);                       // (32, 32) = 1024 blocks
    moments_fused<<<g1, 256>>>(mk);

    dim3 g2(PIX_PER_IMG / (256 * SHIFT_ELEMS), B_);   // (128, 32)
    shift_kernel<<<g2, 256>>>((const float4*)x, (float4*)d_out);
}

// round 7
// speedup vs baseline: 1.0190x; 1.0190x over previous
#include <cuda_runtime.h>
#include <stdint.h>

#define B_  32
#define H_  512
#define W_  512
#define PIX_PER_IMG (H_ * W_)                    // 262144
#define CHUNKS 16                                // moments blocks per batch
#define F4_PER_CHUNK (PIX_PER_IMG / CHUNKS / 4)  // 4096 float4 per block
#define GROUPS 2
#define GSIZE  8                                 // 8 float4 in flight per group

// Scratch (no allocations allowed)
__device__ float        g_part[B_ * CHUNKS * 3];
__device__ int          g_shift[B_ * 2];         // (dx, dy) per batch
__device__ unsigned int g_cnt[B_];               // zero-init; self-reset each launch

// ---------------------------------------------------------------------------
// Stage 1 (fused): per-chunk partial moments of mk + last-block finalize.
// 16 float4 per thread in 2 groups of 8 (MLP=8, 32 data regs, no spill).
// Deterministic: fixed accumulation order, butterfly shuffle reduce,
// fixed-order finalize tree regardless of arrival order.
// ---------------------------------------------------------------------------
__global__ __launch_bounds__(256) void moments_fused(const float* __restrict__ mk)
{
    const int b     = blockIdx.y;
    const int chunk = blockIdx.x;       // 0..15
    const int t     = threadIdx.x;      // 0..255
    const int lane  = t & 31;
    const int wid   = t >> 5;           // 0..7

    const float4* base =
        (const float4*)(mk + (size_t)b * PIX_PER_IMG) + chunk * F4_PER_CHUNK;

    float s0 = 0.f, s1 = 0.f, s2 = 0.f;
#pragma unroll
    for (int g = 0; g < GROUPS; g++) {
        float4 v[GSIZE];
#pragma unroll
        for (int i = 0; i < GSIZE; i++)
            v[i] = __ldcs(&base[t + (g * GSIZE + i) * 256]);
#pragma unroll
        for (int i = 0; i < GSIZE; i++) {
            const int p = chunk * (F4_PER_CHUNK * 4) + (t + (g * GSIZE + i) * 256) * 4;
            const int h = p >> 9;
            const int w = p & (W_ - 1);
            const float ry  = (float)(h - (H_ / 2));
            const float rx0 = (float)(w - (W_ / 2));
            const float sum = v[i].x + v[i].y + v[i].z + v[i].w;
            s0 += sum;
            s2 += ry * sum;
            s1 += rx0 * v[i].x + (rx0 + 1.f) * v[i].y + (rx0 + 2.f) * v[i].z
                + (rx0 + 3.f) * v[i].w;
        }
    }

    // Warp butterfly reduce (deterministic fixed order)
#pragma unroll
    for (int m = 16; m > 0; m >>= 1) {
        s0 += __shfl_xor_sync(0xffffffffu, s0, m);
        s1 += __shfl_xor_sync(0xffffffffu, s1, m);
        s2 += __shfl_xor_sync(0xffffffffu, s2, m);
    }

    __shared__ float w0[8], w1[8], w2[8];
    if (lane == 0) { w0[wid] = s0; w1[wid] = s1; w2[wid] = s2; }
    __syncthreads();

    __shared__ bool isLast;
    if (t == 0) {
        float r0 = 0.f, r1 = 0.f, r2 = 0.f;
#pragma unroll
        for (int i = 0; i < 8; i++) { r0 += w0[i]; r1 += w1[i]; r2 += w2[i]; }
        const int o = (b * CHUNKS + chunk) * 3;
        g_part[o + 0] = r0;
        g_part[o + 1] = r1;
        g_part[o + 2] = r2;
        __threadfence();
        isLast = (atomicAdd(&g_cnt[b], 1u) == CHUNKS - 1);
    }
    __syncthreads();

    if (isLast) {
        __shared__ float f0[CHUNKS], f1[CHUNKS], f2[CHUNKS];
        if (t < CHUNKS) {
            const int o = (b * CHUNKS + t) * 3;
            f0[t] = g_part[o + 0];
            f1[t] = g_part[o + 1];
            f2[t] = g_part[o + 2];
        }
        __syncthreads();
#pragma unroll
        for (int st = CHUNKS / 2; st > 0; st >>= 1) {
            if (t < st) {
                f0[t] += f0[t + st];
                f1[t] += f1[t + st];
                f2[t] += f2[t + st];
            }
            __syncthreads();
        }
        if (t == 0) {
            const float m00 = fmaxf(0.001f, f0[0]);
            // rintf = round-half-even, matching jnp.round
            g_shift[b * 2 + 0] = (int)rintf(f1[0] / m00);   // dx
            g_shift[b * 2 + 1] = (int)rintf(f2[0] / m00);   // dy
            g_cnt[b] = 0u;      // self-reset -> state-clean for next replay
            __threadfence();
        }
    }
}

// ---------------------------------------------------------------------------
// Stage 2: shifted copy. 8 pixels (8x float4) per thread; independent loads
// front-batched for MLP=8; streaming hints (single-touch data).
// out[b,h,w] = x[b, h+dy, w+dx] if in-bounds else 0   (clamped-pad semantics)
// ---------------------------------------------------------------------------
#define SHIFT_ELEMS 8
__global__ __launch_bounds__(256) void shift_kernel(const float4* __restrict__ x,
                                                    float4* __restrict__ out)
{
    const int b    = blockIdx.y;
    const int base = blockIdx.x * (256 * SHIFT_ELEMS);   // pixel base in image
    const int t    = threadIdx.x;

    const int dx = g_shift[b * 2 + 0];
    const int dy = g_shift[b * 2 + 1];

    const float4* xb = x + ((size_t)b << 18);
    float4* ob       = out + ((size_t)b << 18);

    float4 v[SHIFT_ELEMS];
#pragma unroll
    for (int k = 0; k < SHIFT_ELEMS; k++) {
        const int p = base + k * 256 + t;
        const int h = p >> 9;
        const int w = p & (W_ - 1);
        const int sh = h + dy;
        const int sw = w + dx;
        v[k] = make_float4(0.f, 0.f, 0.f, 0.f);
        if ((unsigned)sh < (unsigned)H_ && (unsigned)sw < (unsigned)W_)
            v[k] = __ldcs(&xb[(sh << 9) + sw]);
    }
#pragma unroll
    for (int k = 0; k < SHIFT_ELEMS; k++)
        __stcs(&ob[base + k * 256 + t], v[k]);
}

// ---------------------------------------------------------------------------
extern "C" void kernel_launch(void* const* d_in, const int* in_sizes, int n_in,
                              void* d_out, int out_size)
{
    const float* x  = (const float*)d_in[0];   // [32,512,512,4]
    const float* mk = (const float*)d_in[1];   // [32,512,512,1]

    dim3 g1(CHUNKS, B_);                       // (16, 32) = 512 blocks
    moments_fused<<<g1, 256>>>(mk);

    dim3 g2(PIX_PER_IMG / (256 * SHIFT_ELEMS), B_);   // (128, 32)
    shift_kernel<<<g2, 256>>>((const float4*)x, (float4*)d_out);
}